// round 6
// baseline (speedup 1.0000x reference)
#include <cuda_runtime.h>
#include <cstdint>

#define EMBED     1024
#define STEPS     8
#define NF        16     // 2*STEPS features
#define NFP       8      // f32x2 feature pairs
#define TOK_TILE  128    // tokens per CTA
#define NTHREADS  256    // 256 threads * 4 dims = 1024 embed dims
#define DPT       4      // embed dims per thread

__device__ __forceinline__ unsigned long long pack2(float a, float b) {
    unsigned long long r;
    asm("mov.b64 %0, {%1, %2};" : "=l"(r) : "f"(a), "f"(b));
    return r;
}

__device__ __forceinline__ void load_feats(const float* fs, unsigned long long* f2) {
    const ulonglong2* fp = reinterpret_cast<const ulonglong2*>(fs);
    ulonglong2 qa = fp[0], qb = fp[1], qc = fp[2], qd = fp[3];
    f2[0] = qa.x; f2[1] = qa.y; f2[2] = qb.x; f2[3] = qb.y;
    f2[4] = qc.x; f2[5] = qc.y; f2[6] = qd.x; f2[7] = qd.y;
}

__device__ __forceinline__ void copy_feats(const unsigned long long* src, unsigned long long* dst) {
    #pragma unroll
    for (int i = 0; i < NFP; ++i) dst[i] = src[i];
}

// One token's worth of work: 32 FFMA2 (4 independent chains) + epilogue + STG.128
__device__ __forceinline__ void token_body(const unsigned long long* f2,
                                           const unsigned long long wreg[DPT][NFP],
                                           float* outp) {
    unsigned long long a0 = 0ull, a1 = 0ull, a2 = 0ull, a3 = 0ull;
    #pragma unroll
    for (int p = 0; p < NFP; ++p) {
        asm("fma.rn.f32x2 %0, %1, %2, %0;" : "+l"(a0) : "l"(f2[p]), "l"(wreg[0][p]));
        asm("fma.rn.f32x2 %0, %1, %2, %0;" : "+l"(a1) : "l"(f2[p]), "l"(wreg[1][p]));
        asm("fma.rn.f32x2 %0, %1, %2, %0;" : "+l"(a2) : "l"(f2[p]), "l"(wreg[2][p]));
        asm("fma.rn.f32x2 %0, %1, %2, %0;" : "+l"(a3) : "l"(f2[p]), "l"(wreg[3][p]));
    }
    float l0, h0, l1, h1, l2, h2, l3, h3;
    asm("mov.b64 {%0, %1}, %2;" : "=f"(l0), "=f"(h0) : "l"(a0));
    asm("mov.b64 {%0, %1}, %2;" : "=f"(l1), "=f"(h1) : "l"(a1));
    asm("mov.b64 {%0, %1}, %2;" : "=f"(l2), "=f"(h2) : "l"(a2));
    asm("mov.b64 {%0, %1}, %2;" : "=f"(l3), "=f"(h3) : "l"(a3));
    float4 o = make_float4(l0 + h0, l1 + h1, l2 + h2, l3 + h3);
    __stcs(reinterpret_cast<float4*>(outp), o);
}

__global__ void __launch_bounds__(NTHREADS, 2)
fractal_embed_kernel(const int*   __restrict__ token_ids,
                     const float* __restrict__ c_table,
                     const float* __restrict__ W,
                     const float* __restrict__ scale_p,
                     float*       __restrict__ out,
                     int n_tokens)
{
    __shared__ __align__(16) float feats_s[TOK_TILE][NF];

    const int tid      = threadIdx.x;
    const int tok_base = blockIdx.x * TOK_TILE;
    if (tok_base >= n_tokens) return;
    const float scale  = *scale_p;

    // ---- Phase A: Julia features (128 threads, one token each) ----
    if (tid < TOK_TILE && tok_base + tid < n_tokens) {
        const int   tok = token_ids[tok_base + tid];
        const float cr  = c_table[2 * tok];
        const float ci  = c_table[2 * tok + 1];
        float zr = 0.f, zi = 0.f;
        #pragma unroll
        for (int s = 0; s < STEPS; ++s) {
            const float nzr = zr * zr - zi * zi + cr;
            const float nzi = 2.f * zr * zi + ci;
            zr = nzr; zi = nzi;
            feats_s[tid][2 * s]     = zr;
            feats_s[tid][2 * s + 1] = zi;
        }
    }

    // ---- W slice: 4 rows x 16 feats, scale folded, f32x2-packed (32 u64) ----
    const int d0 = tid * DPT;
    unsigned long long wreg[DPT][NFP];
    {
        const float2* wp = reinterpret_cast<const float2*>(W + (size_t)d0 * NF);
        #pragma unroll
        for (int j = 0; j < DPT; ++j) {
            #pragma unroll
            for (int p = 0; p < NFP; ++p) {
                float2 w = wp[j * NFP + p];
                wreg[j][p] = pack2(w.x * scale, w.y * scale);
            }
        }
    }
    __syncthreads();

    // ---- Phase B: single-token sweep, register-double-buffered feats ----
    float* outp = out + (size_t)tok_base * EMBED + d0;
    const int tmax = n_tokens - tok_base;

    if (tmax >= TOK_TILE) {
        unsigned long long fcur[NFP], fnext[NFP];
        load_feats(feats_s[0], fcur);          // prologue
        #pragma unroll 1
        for (int t = 0; t < TOK_TILE - 1; ++t) {
            load_feats(feats_s[t + 1], fnext); // prefetch: LDS latency hidden by FMAs below
            token_body(fcur, wreg, outp);
            copy_feats(fnext, fcur);
            outp += EMBED;
        }
        token_body(fcur, wreg, outp);          // epilogue token
    } else {
        #pragma unroll 1
        for (int t = 0; t < tmax; ++t) {
            unsigned long long fA[NFP];
            load_feats(feats_s[t], fA);
            token_body(fA, wreg, outp);
            outp += EMBED;
        }
    }
}

extern "C" void kernel_launch(void* const* d_in, const int* in_sizes, int n_in,
                              void* d_out, int out_size)
{
    const int*   token_ids = (const int*)  d_in[0];
    const float* c_table   = (const float*)d_in[1];
    const float* W         = (const float*)d_in[2];
    const float* scale_p   = (const float*)d_in[3];
    float*       out       = (float*)d_out;

    const int n_tokens = in_sizes[0];
    const int blocks   = (n_tokens + TOK_TILE - 1) / TOK_TILE;
    fractal_embed_kernel<<<blocks, NTHREADS>>>(token_ids, c_table, W, scale_p, out, n_tokens);
}

// round 7
// speedup vs baseline: 1.0950x; 1.0950x over previous
#include <cuda_runtime.h>
#include <cstdint>

#define EMBED     1024
#define STEPS     8
#define NF        16     // 2*STEPS features
#define NFP       8      // f32x2 feature pairs
#define TOK_TILE  128    // tokens per CTA
#define NTHREADS  256    // 256 threads * 4 dims = 1024 embed dims
#define DPT       4      // embed dims per thread

__device__ __forceinline__ unsigned long long pack2(float a, float b) {
    unsigned long long r;
    asm("mov.b64 %0, {%1, %2};" : "=l"(r) : "f"(a), "f"(b));
    return r;
}

__device__ __forceinline__ void load_feats(const float* fs, unsigned long long* f2) {
    const ulonglong2* fp = reinterpret_cast<const ulonglong2*>(fs);
    ulonglong2 qa = fp[0], qb = fp[1], qc = fp[2], qd = fp[3];
    f2[0] = qa.x; f2[1] = qa.y; f2[2] = qb.x; f2[3] = qb.y;
    f2[4] = qc.x; f2[5] = qc.y; f2[6] = qd.x; f2[7] = qd.y;
}

// One token: 32 FFMA2 (4 independent chains) + horizontal add + STG.128
__device__ __forceinline__ void token_body(const unsigned long long* f2,
                                           const unsigned long long wreg[DPT][NFP],
                                           float* outp) {
    unsigned long long a0 = 0ull, a1 = 0ull, a2 = 0ull, a3 = 0ull;
    #pragma unroll
    for (int p = 0; p < NFP; ++p) {
        asm("fma.rn.f32x2 %0, %1, %2, %0;" : "+l"(a0) : "l"(f2[p]), "l"(wreg[0][p]));
        asm("fma.rn.f32x2 %0, %1, %2, %0;" : "+l"(a1) : "l"(f2[p]), "l"(wreg[1][p]));
        asm("fma.rn.f32x2 %0, %1, %2, %0;" : "+l"(a2) : "l"(f2[p]), "l"(wreg[2][p]));
        asm("fma.rn.f32x2 %0, %1, %2, %0;" : "+l"(a3) : "l"(f2[p]), "l"(wreg[3][p]));
    }
    float l0, h0, l1, h1, l2, h2, l3, h3;
    asm("mov.b64 {%0, %1}, %2;" : "=f"(l0), "=f"(h0) : "l"(a0));
    asm("mov.b64 {%0, %1}, %2;" : "=f"(l1), "=f"(h1) : "l"(a1));
    asm("mov.b64 {%0, %1}, %2;" : "=f"(l2), "=f"(h2) : "l"(a2));
    asm("mov.b64 {%0, %1}, %2;" : "=f"(l3), "=f"(h3) : "l"(a3));
    float4 o = make_float4(l0 + h0, l1 + h1, l2 + h2, l3 + h3);
    __stcs(reinterpret_cast<float4*>(outp), o);
}

__global__ void __launch_bounds__(NTHREADS, 2)
fractal_embed_kernel(const int*   __restrict__ token_ids,
                     const float* __restrict__ c_table,
                     const float* __restrict__ W,
                     const float* __restrict__ scale_p,
                     float*       __restrict__ out,
                     int n_tokens)
{
    // +2 pad rows: steady-state loop prefetches one token past the tile;
    // the padded row is loaded (garbage) but never consumed.
    __shared__ __align__(16) float feats_s[TOK_TILE + 2][NF];

    const int tid      = threadIdx.x;
    const int tok_base = blockIdx.x * TOK_TILE;
    if (tok_base >= n_tokens) return;
    const float scale  = *scale_p;

    // ---- Phase A: Julia features (128 threads, one token each) ----
    if (tid < TOK_TILE && tok_base + tid < n_tokens) {
        const int   tok = token_ids[tok_base + tid];
        const float cr  = c_table[2 * tok];
        const float ci  = c_table[2 * tok + 1];
        float zr = 0.f, zi = 0.f;
        #pragma unroll
        for (int s = 0; s < STEPS; ++s) {
            const float nzr = zr * zr - zi * zi + cr;
            const float nzi = 2.f * zr * zi + ci;
            zr = nzr; zi = nzi;
            feats_s[tid][2 * s]     = zr;
            feats_s[tid][2 * s + 1] = zi;
        }
    }

    // ---- W slice: 4 rows x 16 feats, scale folded, f32x2-packed (32 u64) ----
    const int d0 = tid * DPT;
    unsigned long long wreg[DPT][NFP];
    {
        const float2* wp = reinterpret_cast<const float2*>(W + (size_t)d0 * NF);
        #pragma unroll
        for (int j = 0; j < DPT; ++j) {
            #pragma unroll
            for (int p = 0; p < NFP; ++p) {
                float2 w = wp[j * NFP + p];
                wreg[j][p] = pack2(w.x * scale, w.y * scale);
            }
        }
    }
    __syncthreads();

    // ---- Phase B: 2-deep software pipeline, zero-copy buffer rotation ----
    float* outp = out + (size_t)tok_base * EMBED + d0;
    const int tmax = n_tokens - tok_base;

    if (tmax >= TOK_TILE) {
        unsigned long long fbuf[NFP], gbuf[NFP];
        load_feats(feats_s[0], fbuf);                 // prologue
        #pragma unroll 1
        for (int t = 0; t < TOK_TILE; t += 2) {
            load_feats(feats_s[t + 1], gbuf);         // prefetch t+1
            token_body(fbuf, wreg, outp);             // consume t (hides gbuf LDS)
            load_feats(feats_s[t + 2], fbuf);         // prefetch t+2 (pad row at t=126 ok)
            token_body(gbuf, wreg, outp + EMBED);     // consume t+1 (hides fbuf LDS)
            outp += 2 * EMBED;
        }
    } else {
        #pragma unroll 1
        for (int t = 0; t < tmax; ++t) {
            unsigned long long fA[NFP];
            load_feats(feats_s[t], fA);
            token_body(fA, wreg, outp);
            outp += EMBED;
        }
    }
}

extern "C" void kernel_launch(void* const* d_in, const int* in_sizes, int n_in,
                              void* d_out, int out_size)
{
    const int*   token_ids = (const int*)  d_in[0];
    const float* c_table   = (const float*)d_in[1];
    const float* W         = (const float*)d_in[2];
    const float* scale_p   = (const float*)d_in[3];
    float*       out       = (float*)d_out;

    const int n_tokens = in_sizes[0];
    const int blocks   = (n_tokens + TOK_TILE - 1) / TOK_TILE;
    fractal_embed_kernel<<<blocks, NTHREADS>>>(token_ids, c_table, W, scale_p, out, n_tokens);
}